// round 5
// baseline (speedup 1.0000x reference)
#include <cuda_runtime.h>
#include <cuda_bf16.h>
#include <math.h>
#include <stdint.h>

// ============================ device scratch ============================
__device__ float g_scores[256 * 256];
__device__ int   g_idxL[256];
__device__ int   g_idxR[256];
__device__ float g_xent[6144];
__device__ float g_pu[64 * 6144];
__device__ float g_pv[64 * 6144];
// [tile(4: nH,nL,gH,gL)][jt(12)][kt(12)] tiles of 64j x 64k bf16 (8192B)
__device__ __align__(16) __nv_bfloat16 g_Wprep[4 * 12 * 12 * 4096];

#define NJT 12
#define NKT 12
#define NIT (NJT * NKT)

// SMEM: A 2x64KB (hi+lo), W 2x32KB, meta 1KB, score 8KB = 205824 B
#define OFF_AHI(st) ((st) * 65536)
#define OFF_ALO(st) ((st) * 65536 + 32768)
#define OFF_WT(st)  (131072 + (st) * 32768)
#define OFF_META    196608
#define OFF_SC      197632
#define SMEM_BYTES  205824

// ============================ helpers ============================
__device__ __forceinline__ uint32_t smem_u32(const void* p) {
    uint32_t a;
    asm("{ .reg .u64 t; cvta.to.shared.u64 t, %1; cvt.u32.u64 %0, t; }" : "=r"(a) : "l"(p));
    return a;
}
__device__ __forceinline__ void cp16(uint32_t s, const void* g) {
    asm volatile("cp.async.cg.shared.global [%0], [%1], 16;" :: "r"(s), "l"(g));
}
__device__ __forceinline__ void cp_commit() { asm volatile("cp.async.commit_group;"); }
__device__ __forceinline__ void cp_wait0()  { asm volatile("cp.async.wait_group 0;" ::: "memory"); }
__device__ __forceinline__ void ldsm4(uint32_t& r0, uint32_t& r1, uint32_t& r2, uint32_t& r3,
                                      uint32_t a) {
    asm volatile("ldmatrix.sync.aligned.m8n8.x4.shared.b16 {%0,%1,%2,%3}, [%4];"
                 : "=r"(r0), "=r"(r1), "=r"(r2), "=r"(r3) : "r"(a));
}
__device__ __forceinline__ void mma16816(float* d, const uint32_t* a, const uint32_t* b) {
    asm volatile("mma.sync.aligned.m16n8k16.row.col.f32.bf16.bf16.f32 "
                 "{%0,%1,%2,%3},{%4,%5,%6,%7},{%8,%9},{%0,%1,%2,%3};"
                 : "+f"(d[0]), "+f"(d[1]), "+f"(d[2]), "+f"(d[3])
                 : "r"(a[0]), "r"(a[1]), "r"(a[2]), "r"(a[3]), "r"(b[0]), "r"(b[1]));
}
__device__ __forceinline__ void split2(float d0, float d1, uint32_t& hi, uint32_t& lo) {
    union { __nv_bfloat162 b; uint32_t u; } ch, cl;
    ch.b = __floats2bfloat162_rn(d0, d1);
    float f0 = __uint_as_float(ch.u << 16);
    float f1 = __uint_as_float(ch.u & 0xFFFF0000u);
    cl.b = __floats2bfloat162_rn(d0 - f0, d1 - f1);
    hi = ch.u; lo = cl.u;
}

__global__ void dummy_kernel() {}

// ============================ Kernel P: weight prep ============================
// Tile layout: [q][jt][kt] of 64j x 64k bf16; row=j&63 (128B), chunk=k/8,
// swizzle: chunk ^= row&7.
__global__ __launch_bounds__(256) void prep_w(const float* __restrict__ Wn,
                                              const float* __restrict__ Wg)
{
    int tid = blockIdx.x * 256 + threadIdx.x;      // 147456 = 2*96*768
    int mat = tid / 73728;
    int rem = tid - mat * 73728;
    int kc  = rem / 768;                            // 0..95, k0 = kc*8
    int j   = rem - kc * 768;
    const float* W = mat ? Wg : Wn;
    int k0 = kc * 8;
    uint32_t hi[4], lo[4];
    #pragma unroll
    for (int p = 0; p < 4; ++p)
        split2(W[(size_t)(k0 + 2 * p) * 768 + j], W[(size_t)(k0 + 2 * p + 1) * 768 + j],
               hi[p], lo[p]);
    int kt = kc >> 3, c = kc & 7;
    int jt = j >> 6, row = j & 63;
    int off = row * 128 + ((c ^ (row & 7)) << 4);
    char* bh = (char*)g_Wprep + (size_t)(((mat * 2 + 0) * NJT + jt) * NKT + kt) * 8192 + off;
    char* bl = (char*)g_Wprep + (size_t)(((mat * 2 + 1) * NJT + jt) * NKT + kt) * 8192 + off;
    *(uint4*)bh = make_uint4(hi[0], hi[1], hi[2], hi[3]);
    *(uint4*)bl = make_uint4(lo[0], lo[1], lo[2], lo[3]);
}

// ============================ Kernel A: HMMA score GEMM (k64) ============================
__device__ __forceinline__ void build_a(char* smem, const float* __restrict__ Rg,
                                        const float* __restrict__ Lrow,
                                        int kt, int st, int t)
{
    const float* Rr = Rg + (size_t)t * 768 + kt * 64;
    const float* Lr = Lrow + kt * 64;
    char* hb = smem + OFF_AHI(st);
    char* lb = smem + OFF_ALO(st);
    #pragma unroll
    for (int c = 0; c < 8; ++c) {
        float4 r0 = *(const float4*)(Rr + c * 8);
        float4 r1 = *(const float4*)(Rr + c * 8 + 4);
        float4 l0 = *(const float4*)(Lr + c * 8);
        float4 l1 = *(const float4*)(Lr + c * 8 + 4);
        uint32_t h0, h1, h2, h3, e0, e1, e2, e3;
        split2(fabsf(l0.x - r0.x), fabsf(l0.y - r0.y), h0, e0);
        split2(fabsf(l0.z - r0.z), fabsf(l0.w - r0.w), h1, e1);
        split2(fabsf(l1.x - r1.x), fabsf(l1.y - r1.y), h2, e2);
        split2(fabsf(l1.z - r1.z), fabsf(l1.w - r1.w), h3, e3);
        int off = t * 128 + ((c ^ (t & 7)) << 4);
        *(uint4*)(hb + off) = make_uint4(h0, h1, h2, h3);
        *(uint4*)(lb + off) = make_uint4(e0, e1, e2, e3);
    }
}
__device__ __forceinline__ void copy_w(uint32_t sb, int jt, int kt, int st, int t)
{
    #pragma unroll
    for (int q = 0; q < 4; ++q) {
        const char* g = (const char*)g_Wprep + (size_t)((q * NJT + jt) * NKT + kt) * 8192;
        cp16(sb + OFF_WT(st) + q * 8192 + t * 32,      g + t * 32);
        cp16(sb + OFF_WT(st) + q * 8192 + t * 32 + 16, g + t * 32 + 16);
    }
}

__global__ __launch_bounds__(256, 1) void score_kernel(
    const float* __restrict__ L, const float* __restrict__ R,
    const float* __restrict__ bn, const float* __restrict__ bg,
    const float* __restrict__ Wl)
{
    extern __shared__ __align__(1024) char smem[];
    const uint32_t sb = smem_u32(smem);
    const int t = threadIdx.x;
    const int lane = t & 31;
    const int wm = (t >> 5) >> 1, wn = (t >> 5) & 1;
    const int bl = blockIdx.x;
    const float* Lrow = L + (size_t)bl * 768;

    copy_w(sb, 0, 0, 0, t);
    cp_commit();
    build_a(smem, R, Lrow, 0, 0, t);
    cp_wait0();
    __syncthreads();

    float scoreAcc[4][2] = {};

    for (int jt = 0; jt < NJT; ++jt) {
        float Uacc[4][4][4] = {};
        float Vacc[4][4][4] = {};
        if (t < 64) {
            float* sm = (float*)(smem + OFF_META);
            int j = jt * 64 + t;
            sm[t] = bn[j]; sm[64 + t] = bg[j]; sm[128 + t] = Wl[j]; sm[192 + t] = Lrow[j];
        }
        for (int kt = 0; kt < NKT; ++kt) {
            const int i = jt * NKT + kt;
            const int st = i & 1;
            if (i + 1 < NIT) {
                const int jn = (kt == NKT - 1) ? jt + 1 : jt;
                const int kn = (kt == NKT - 1) ? 0 : kt + 1;
                copy_w(sb, jn, kn, st ^ 1, t);
                cp_commit();
                build_a(smem, R, Lrow, kn, st ^ 1, t);
            }
            #pragma unroll
            for (int s = 0; s < 4; ++s) {
                uint32_t B[4][4][2];
                #pragma unroll
                for (int q = 0; q < 4; ++q) {
                    #pragma unroll
                    for (int h = 0; h < 2; ++h) {
                        int row = wn * 32 + h * 16 + ((lane >> 4) & 1) * 8 + (lane & 7);
                        int chunk = s * 2 + ((lane >> 3) & 1);
                        uint32_t addr = sb + OFF_WT(st) + q * 8192 +
                                        row * 128 + ((chunk ^ (row & 7)) << 4);
                        ldsm4(B[q][2 * h][0], B[q][2 * h][1],
                              B[q][2 * h + 1][0], B[q][2 * h + 1][1], addr);
                    }
                }
                #pragma unroll
                for (int mt = 0; mt < 4; ++mt) {
                    uint32_t A[4];
                    int row = wm * 64 + mt * 16 + ((lane >> 3) & 1) * 8 + (lane & 7);
                    int chunk = s * 2 + ((lane >> 4) & 1);
                    uint32_t swz = row * 128 + ((chunk ^ (row & 7)) << 4);
                    ldsm4(A[0], A[1], A[2], A[3], sb + OFF_AHI(st) + swz);
                    #pragma unroll
                    for (int nt = 0; nt < 4; ++nt) {
                        mma16816(Uacc[mt][nt], A, B[0][nt]);
                        mma16816(Uacc[mt][nt], A, B[1][nt]);
                        mma16816(Vacc[mt][nt], A, B[2][nt]);
                        mma16816(Vacc[mt][nt], A, B[3][nt]);
                    }
                    ldsm4(A[0], A[1], A[2], A[3], sb + OFF_ALO(st) + swz);
                    #pragma unroll
                    for (int nt = 0; nt < 4; ++nt) {
                        mma16816(Uacc[mt][nt], A, B[0][nt]);
                        mma16816(Vacc[mt][nt], A, B[2][nt]);
                    }
                }
            }
            if (kt == NKT - 1) {
                const float* smf = (const float*)(smem + OFF_META);
                #pragma unroll
                for (int mt = 0; mt < 4; ++mt) {
                    #pragma unroll
                    for (int hf = 0; hf < 2; ++hf) {
                        const int r = wm * 64 + mt * 16 + hf * 8 + (lane >> 2);
                        const float* Rr = R + (size_t)r * 768 + jt * 64;
                        float sc = scoreAcc[mt][hf];
                        #pragma unroll
                        for (int nt = 0; nt < 4; ++nt) {
                            #pragma unroll
                            for (int e = 0; e < 2; ++e) {
                                const int jl = wn * 32 + nt * 8 + ((lane & 3) << 1) + e;
                                const float x = fabsf(smf[192 + jl] - Rr[jl]);
                                const float u = Uacc[mt][nt][hf * 2 + e] + smf[jl];
                                const float v = Vacc[mt][nt][hf * 2 + e] + smf[64 + jl];
                                const float g = 1.f / (1.f + __expf(-v));
                                sc += (fmaxf(u, 0.f) * g + (1.f - g) * x) * smf[128 + jl];
                            }
                        }
                        scoreAcc[mt][hf] = sc;
                    }
                }
            }
            cp_wait0();
            __syncthreads();
        }
    }

    float* sS = (float*)(smem + OFF_SC);
    #pragma unroll
    for (int mt = 0; mt < 4; ++mt)
        #pragma unroll
        for (int hf = 0; hf < 2; ++hf)
            sS[(wm * 64 + mt * 16 + hf * 8 + (lane >> 2)) * 8 + wn * 4 + (lane & 3)] =
                scoreAcc[mt][hf];
    __syncthreads();
    float s = 0.f;
    #pragma unroll
    for (int q = 0; q < 8; ++q) s += sS[t * 8 + q];
    g_scores[bl * 256 + t] = s;
}

// ============================ Kernel B: argmax ============================
__global__ __launch_bounds__(256) void argmax_kernel()
{
    const int b = blockIdx.x;
    const int t = threadIdx.x;
    const bool col = (b >= 256);
    const int idx = col ? (b - 256) : b;
    float v = col ? g_scores[t * 256 + idx] : g_scores[idx * 256 + t];
    __shared__ float sv[256];
    __shared__ int   si[256];
    sv[t] = v; si[t] = t;
    __syncthreads();
    for (int s = 128; s > 0; s >>= 1) {
        if (t < s) {
            if (sv[t + s] > sv[t] || (sv[t + s] == sv[t] && si[t + s] < si[t])) {
                sv[t] = sv[t + s]; si[t] = si[t + s];
            }
        }
        __syncthreads();
    }
    if (t == 0) { if (col) g_idxR[idx] = si[0]; else g_idxL[idx] = si[0]; }
}

// ============================ Kernel C: attribute matching ============================
__global__ __launch_bounds__(256) void attr_kernel(
    const float* __restrict__ L, const float* __restrict__ R,
    const float* __restrict__ AEl, const float* __restrict__ AEr,
    const float* __restrict__ empty,
    const int* __restrict__ lensL, const int* __restrict__ lensR)
{
    const int b = blockIdx.x;
    const int side = b >> 2;
    const int a = b & 3;
    const float* T  = side ? R : L;
    const float* O  = side ? L : R;
    const int*   ix = side ? g_idxR : g_idxL;
    const float* AE = side ? AEr : AEl;
    const int* lens = side ? lensR : lensL;
    const int t = threadIdx.x, wid = t >> 5, lane = t & 31;

    int start = 0;
    for (int i = 0; i < a; ++i) start += lens[i];
    const int len = lens[a];
    float* rep = g_xent + (size_t)(side * 4 + a) * 768;

    if (len == 0) {
        for (int d = t; d < 768; d += 256) rep[d] = empty[d];
        return;
    }
    __shared__ float sw[256];
    __shared__ float red[256];

    // phase 1: warp-per-token coalesced dots
    const float* ae = AE + (size_t)a * 768;
    for (int i = wid; i < len; i += 8) {
        const float* tok = T + (size_t)(start + i) * 768;
        float acc = 0.f;
        #pragma unroll 4
        for (int d = lane; d < 768; d += 32) acc = fmaf(tok[d], ae[d], acc);
        #pragma unroll
        for (int o = 16; o > 0; o >>= 1) acc += __shfl_xor_sync(0xFFFFFFFF, acc, o);
        if (lane == 0) sw[i] = acc;
    }
    __syncthreads();
    // phase 2: softmax over len
    float s = (t < len) ? sw[t] : -1e30f;
    red[t] = s;
    __syncthreads();
    for (int st = 128; st > 0; st >>= 1) {
        if (t < st) red[t] = fmaxf(red[t], red[t + st]);
        __syncthreads();
    }
    const float m = red[0];
    __syncthreads();
    const float e = (t < len) ? __expf(s - m) : 0.f;
    red[t] = e;
    __syncthreads();
    for (int st = 128; st > 0; st >>= 1) {
        if (t < st) red[t] += red[t + st];
        __syncthreads();
    }
    const float z = red[0];
    __syncthreads();
    sw[t] = e / z;
    __syncthreads();
    // phase 3: weighted abs-diff sums
    for (int d = t; d < 768; d += 256) {
        float acc = 0.f;
        for (int i = 0; i < len; ++i) {
            const int tok = start + i;
            acc = fmaf(sw[i],
                       fabsf(T[(size_t)tok * 768 + d] - O[(size_t)ix[tok] * 768 + d]), acc);
        }
        rep[d] = acc;
    }
}

// ============================ Kernel D: entity matvec partials ============================
__global__ __launch_bounds__(256) void ent_partial(
    const float* __restrict__ Wn, const float* __restrict__ Wg)
{
    const int j  = blockIdx.x * 256 + threadIdx.x;
    const int rs = blockIdx.y;                      // 0..63
    const int i0 = rs * 96;
    float au = 0.f, av = 0.f;
    #pragma unroll 8
    for (int i = 0; i < 96; ++i) {
        const float xi = g_xent[i0 + i];
        au = fmaf(xi, __ldg(Wn + (size_t)(i0 + i) * 6144 + j), au);
        av = fmaf(xi, __ldg(Wg + (size_t)(i0 + i) * 6144 + j), av);
    }
    g_pu[rs * 6144 + j] = au;
    g_pv[rs * 6144 + j] = av;
}

// ============================ Kernel E: finalize ============================
__global__ __launch_bounds__(256) void ent_final(
    const float* __restrict__ bn, const float* __restrict__ bg,
    const float* __restrict__ Wl2, const float* __restrict__ bl2,
    float* __restrict__ out)
{
    const int t = threadIdx.x;
    float l0 = 0.f, l1 = 0.f;
    for (int j = t; j < 6144; j += 256) {
        float u = bn[j], v = bg[j];
        #pragma unroll
        for (int s = 0; s < 64; ++s) { u += g_pu[s * 6144 + j]; v += g_pv[s * 6144 + j]; }
        const float x = g_xent[j];
        const float g = 1.f / (1.f + __expf(-v));
        const float hw = fmaxf(u, 0.f) * g + (1.f - g) * x;
        l0 = fmaf(hw, Wl2[(size_t)j * 2 + 0], l0);
        l1 = fmaf(hw, Wl2[(size_t)j * 2 + 1], l1);
    }
    __shared__ float r0[256], r1[256];
    r0[t] = l0; r1[t] = l1;
    __syncthreads();
    for (int s = 128; s > 0; s >>= 1) {
        if (t < s) { r0[t] += r0[t + s]; r1[t] += r1[t + s]; }
        __syncthreads();
    }
    if (t == 0) {
        const float a = r0[0] + bl2[0];
        const float b = r1[0] + bl2[1];
        const float m = fmaxf(a, b);
        const float ea = __expf(a - m), eb = __expf(b - m);
        const float inv = 1.f / (ea + eb);
        out[0] = ea * inv;
        out[1] = eb * inv;
    }
}

// ============================ launcher ============================
extern "C" void kernel_launch(void* const* d_in, const int* in_sizes, int n_in,
                              void* d_out, int out_size)
{
    const float* left_emb   = (const float*)d_in[0];
    const float* right_emb  = (const float*)d_in[1];
    const float* Wn_tok     = (const float*)d_in[2];
    const float* bn_tok     = (const float*)d_in[3];
    const float* Wg_tok     = (const float*)d_in[4];
    const float* bg_tok     = (const float*)d_in[5];
    const float* W_lin_tok  = (const float*)d_in[6];
    const float* attr_l     = (const float*)d_in[8];
    const float* attr_r     = (const float*)d_in[9];
    const float* Wn_ent     = (const float*)d_in[10];
    const float* bn_ent     = (const float*)d_in[11];
    const float* Wg_ent     = (const float*)d_in[12];
    const float* bg_ent     = (const float*)d_in[13];
    const float* W_lin_ent  = (const float*)d_in[14];
    const float* b_lin_ent  = (const float*)d_in[15];
    const float* empty_attr = (const float*)d_in[16];
    const int*   lensL      = (const int*)d_in[17];
    const int*   lensR      = (const int*)d_in[18];
    float* out = (float*)d_out;

    cudaFuncSetAttribute(score_kernel, cudaFuncAttributeMaxDynamicSharedMemorySize, SMEM_BYTES);

    prep_w<<<576, 256>>>(Wn_tok, Wg_tok);          // launch 0
    dummy_kernel<<<1, 32>>>();                      // launch 1
    dummy_kernel<<<1, 32>>>();                      // launch 2
    score_kernel<<<256, 256, SMEM_BYTES>>>(left_emb, right_emb, bn_tok, bg_tok, W_lin_tok); // 3
    argmax_kernel<<<512, 256>>>();
    attr_kernel<<<8, 256>>>(left_emb, right_emb, attr_l, attr_r,
                            empty_attr, lensL, lensR);
    dim3 gridD(24, 64);
    ent_partial<<<gridD, 256>>>(Wn_ent, Wg_ent);
    ent_final<<<1, 256>>>(bn_ent, bg_ent, W_lin_ent, b_lin_ent, out);
}